// round 1
// baseline (speedup 1.0000x reference)
#include <cuda_runtime.h>
#include <math.h>

#define BATCH 8
#define CIN   128
#define H     112
#define W     112
#define COUT  256
#define OFFC  18     // 2*K*K

// Scratch (allocation-free rule: __device__ globals)
__device__ float g_offset[BATCH * OFFC * H * W];     // (B,18,H,W)
__device__ float g_sampled[BATCH * CIN * H * W];     // (B,128,H,W)

// ---------------------------------------------------------------------------
// Kernel 1: offset conv  x(B,128,H,W) * ow(18,128,3,3) + ob -> g_offset
// Block = one (b,h) row, 128 threads (112 active for w). 18 accumulators/thread.
// ---------------------------------------------------------------------------
#define K1_CK 16
__global__ void offset_conv_kernel(const float* __restrict__ x,
                                   const float* __restrict__ ow,
                                   const float* __restrict__ ob) {
    __shared__ float sW[K1_CK * 9 * OFFC];   // [ci][k][oc]
    __shared__ float sX[K1_CK * 3 * 114];    // [ci][r][j], j -> col j-1 (zero pad)
    const int h = blockIdx.x;
    const int b = blockIdx.y;
    const int tid = threadIdx.x;
    const int w = tid;

    float acc[OFFC];
#pragma unroll
    for (int oc = 0; oc < OFFC; oc++) acc[oc] = ob[oc];

    for (int c0 = 0; c0 < CIN; c0 += K1_CK) {
        // cooperative load of input rows h-1..h+1 for this cin chunk
        for (int e = tid; e < K1_CK * 3 * 114; e += blockDim.x) {
            int ci  = e / (3 * 114);
            int rem = e % (3 * 114);
            int r   = rem / 114;
            int j   = rem % 114;
            int row = h - 1 + r;
            int col = j - 1;
            float v = 0.f;
            if (row >= 0 && row < H && col >= 0 && col < W)
                v = x[((b * CIN + c0 + ci) * H + row) * W + col];
            sX[e] = v;
        }
        // cooperative load of weights for this chunk
        for (int e = tid; e < K1_CK * 9 * OFFC; e += blockDim.x) {
            int ci  = e / (9 * OFFC);
            int rem = e % (9 * OFFC);
            int k   = rem / OFFC;
            int oc  = rem % OFFC;
            sW[e] = ow[(oc * CIN + c0 + ci) * 9 + k];
        }
        __syncthreads();
        if (w < W) {
            for (int ci = 0; ci < K1_CK; ci++) {
                float xv[9];
#pragma unroll
                for (int ky = 0; ky < 3; ky++)
#pragma unroll
                    for (int kx = 0; kx < 3; kx++)
                        xv[ky * 3 + kx] = sX[(ci * 3 + ky) * 114 + w + kx];
#pragma unroll
                for (int k = 0; k < 9; k++) {
                    float xvk = xv[k];
#pragma unroll
                    for (int oc = 0; oc < OFFC; oc++)
                        acc[oc] += xvk * sW[(ci * 9 + k) * OFFC + oc];
                }
            }
        }
        __syncthreads();
    }
    if (w < W) {
#pragma unroll
        for (int oc = 0; oc < OFFC; oc++)
            g_offset[((b * OFFC + oc) * H + h) * W + w] = acc[oc];
    }
}

// ---------------------------------------------------------------------------
// Kernel 2: deformable bilinear sampling, summed over 9 points -> g_sampled
// Block = one (b,h) row, 112 threads (thread = w). Precompute 36 (idx, weight)
// corner pairs in registers, then loop 128 channels with 36 gathers each.
// ---------------------------------------------------------------------------
__device__ __forceinline__ void make_corner(int yi, int xi, float wgt,
                                            int& idx, float& wt) {
    bool valid = (yi >= 0) & (yi < H) & (xi >= 0) & (xi < W);
    int yc = min(max(yi, 0), H - 1);
    int xc = min(max(xi, 0), W - 1);
    idx = yc * W + xc;
    wt = valid ? wgt : 0.f;
}

__global__ void sample_kernel(const float* __restrict__ x) {
    const int h = blockIdx.x;
    const int b = blockIdx.y;
    const int w = threadIdx.x;
    if (w >= W) return;
    const int pix = h * W + w;
    const float* offp = g_offset + (size_t)b * OFFC * H * W + pix;

    int   idx[36];
    float wt[36];
#pragma unroll
    for (int p = 0; p < 9; p++) {
        int ky = p / 3, kx = p % 3;
        float offY = offp[(size_t)p * H * W];
        float offX = offp[(size_t)(9 + p) * H * W];
        float sy = (float)(h + ky - 1) + offY;
        float sx = (float)(w + kx - 1) + offX;
        float fy0 = floorf(sy), fx0 = floorf(sx);
        int y0 = (int)fy0, x0 = (int)fx0;
        float wy = sy - fy0, wx = sx - fx0;
        make_corner(y0,     x0,     (1.f - wy) * (1.f - wx), idx[p*4+0], wt[p*4+0]);
        make_corner(y0,     x0 + 1, (1.f - wy) * wx,         idx[p*4+1], wt[p*4+1]);
        make_corner(y0 + 1, x0,     wy * (1.f - wx),         idx[p*4+2], wt[p*4+2]);
        make_corner(y0 + 1, x0 + 1, wy * wx,                 idx[p*4+3], wt[p*4+3]);
    }

    const float* xb = x + (size_t)b * CIN * H * W;
    float* outb = g_sampled + (size_t)b * CIN * H * W + pix;
#pragma unroll 2
    for (int c = 0; c < CIN; c++) {
        const float* xp = xb + (size_t)c * H * W;
        float acc = 0.f;
#pragma unroll
        for (int q = 0; q < 36; q++) acc += wt[q] * xp[idx[q]];
        outb[(size_t)c * H * W] = acc;
    }
}

// ---------------------------------------------------------------------------
// Kernel 3: main conv  g_sampled(B,128,H,W) * cw(256,128,3,3) -> out
// Block: 64 output channels x full 112-wide row for one (b,h).
// 256 threads: tco in [0,16) -> 4 consecutive co each; tw in [0,16) -> 7 w each.
// Register tile 4co x 7w = 28 accumulators; ~7 FMA per LDS instruction.
// ---------------------------------------------------------------------------
#define CO_TILE 64
#define K3_CK   8
__global__ void __launch_bounds__(256) main_conv_kernel(
        const float* __restrict__ cw, float* __restrict__ out) {
    __shared__ __align__(16) float sIn[K3_CK * 3 * 114];       // [ci][r][j]
    __shared__ __align__(16) float sWt[K3_CK * 9 * CO_TILE];   // [ci][k][co]
    const int cog = blockIdx.x;         // 0..3
    const int h   = blockIdx.y;
    const int b   = blockIdx.z;
    const int tid = threadIdx.x;
    const int tco = tid >> 4;           // 0..15
    const int tw  = tid & 15;           // 0..15
    const int wbase = tw * 7;
    const int co_base = cog * CO_TILE;

    float acc[4][7];
#pragma unroll
    for (int r = 0; r < 4; r++)
#pragma unroll
        for (int i = 0; i < 7; i++) acc[r][i] = 0.f;

    for (int c0 = 0; c0 < CIN; c0 += K3_CK) {
        for (int e = tid; e < K3_CK * 3 * 114; e += 256) {
            int ci  = e / 342;
            int rem = e % 342;
            int r   = rem / 114;
            int j   = rem % 114;
            int row = h - 1 + r;
            int col = j - 1;
            float v = 0.f;
            if (row >= 0 && row < H && col >= 0 && col < W)
                v = g_sampled[((b * CIN + c0 + ci) * H + row) * W + col];
            sIn[e] = v;
        }
        for (int e = tid; e < K3_CK * 9 * CO_TILE; e += 256) {
            int ci  = e / (9 * CO_TILE);
            int rem = e % (9 * CO_TILE);
            int k   = rem / CO_TILE;
            int co  = rem % CO_TILE;
            sWt[e] = cw[((co_base + co) * CIN + c0 + ci) * 9 + k];
        }
        __syncthreads();

#pragma unroll
        for (int ci = 0; ci < K3_CK; ci++) {
#pragma unroll
            for (int ky = 0; ky < 3; ky++) {
                float vals[9];
#pragma unroll
                for (int j = 0; j < 9; j++)
                    vals[j] = sIn[(ci * 3 + ky) * 114 + wbase + j];
#pragma unroll
                for (int kx = 0; kx < 3; kx++) {
                    const float4 wv = *reinterpret_cast<const float4*>(
                        &sWt[(ci * 9 + ky * 3 + kx) * CO_TILE + tco * 4]);
#pragma unroll
                    for (int i = 0; i < 7; i++) {
                        float v = vals[kx + i];
                        acc[0][i] += v * wv.x;
                        acc[1][i] += v * wv.y;
                        acc[2][i] += v * wv.z;
                        acc[3][i] += v * wv.w;
                    }
                }
            }
        }
        __syncthreads();
    }

#pragma unroll
    for (int r = 0; r < 4; r++) {
        int co = co_base + tco * 4 + r;
        float* op = out + (((size_t)b * COUT + co) * H + h) * W + wbase;
#pragma unroll
        for (int i = 0; i < 7; i++) op[i] = acc[r][i];
    }
}

// ---------------------------------------------------------------------------
extern "C" void kernel_launch(void* const* d_in, const int* in_sizes, int n_in,
                              void* d_out, int out_size) {
    const float* x  = (const float*)d_in[0];   // (8,128,112,112)
    const float* ow = (const float*)d_in[1];   // (18,128,3,3)
    const float* ob = (const float*)d_in[2];   // (18)
    const float* cw = (const float*)d_in[3];   // (256,128,3,3)
    float* out = (float*)d_out;                // (8,256,112,112)

    dim3 grid_row(H, BATCH);
    offset_conv_kernel<<<grid_row, 128>>>(x, ow, ob);
    sample_kernel<<<grid_row, 112>>>(x);
    dim3 grid_conv(COUT / CO_TILE, H, BATCH);
    main_conv_kernel<<<grid_conv, 256>>>(cw, out);
}

// round 2
// speedup vs baseline: 1.0005x; 1.0005x over previous
#include <cuda_runtime.h>
#include <math.h>

#define BATCH 8
#define CIN   128
#define H     112
#define W     112
#define COUT  256
#define OFFC  18     // 2*K*K

// Scratch (allocation-free rule: __device__ globals)
__device__ float g_offset[BATCH * OFFC * H * W];     // (B,18,H,W)
__device__ float g_sampled[BATCH * CIN * H * W];     // (B,128,H,W)

// ---------------------------------------------------------------------------
// Kernel 1: offset conv  x(B,128,H,W) * ow(18,128,3,3) + ob -> g_offset
// Block = one (b,h) row, 128 threads (112 active for w). 18 accumulators/thread.
// ---------------------------------------------------------------------------
#define K1_CK 16
__global__ void offset_conv_kernel(const float* __restrict__ x,
                                   const float* __restrict__ ow,
                                   const float* __restrict__ ob) {
    __shared__ float sW[K1_CK * 9 * OFFC];   // [ci][k][oc]
    __shared__ float sX[K1_CK * 3 * 114];    // [ci][r][j], j -> col j-1 (zero pad)
    const int h = blockIdx.x;
    const int b = blockIdx.y;
    const int tid = threadIdx.x;
    const int w = tid;

    float acc[OFFC];
#pragma unroll
    for (int oc = 0; oc < OFFC; oc++) acc[oc] = ob[oc];

    for (int c0 = 0; c0 < CIN; c0 += K1_CK) {
        // cooperative load of input rows h-1..h+1 for this cin chunk
        for (int e = tid; e < K1_CK * 3 * 114; e += blockDim.x) {
            int ci  = e / (3 * 114);
            int rem = e % (3 * 114);
            int r   = rem / 114;
            int j   = rem % 114;
            int row = h - 1 + r;
            int col = j - 1;
            float v = 0.f;
            if (row >= 0 && row < H && col >= 0 && col < W)
                v = x[((b * CIN + c0 + ci) * H + row) * W + col];
            sX[e] = v;
        }
        // cooperative load of weights for this chunk
        for (int e = tid; e < K1_CK * 9 * OFFC; e += blockDim.x) {
            int ci  = e / (9 * OFFC);
            int rem = e % (9 * OFFC);
            int k   = rem / OFFC;
            int oc  = rem % OFFC;
            sW[e] = ow[(oc * CIN + c0 + ci) * 9 + k];
        }
        __syncthreads();
        if (w < W) {
            for (int ci = 0; ci < K1_CK; ci++) {
                float xv[9];
#pragma unroll
                for (int ky = 0; ky < 3; ky++)
#pragma unroll
                    for (int kx = 0; kx < 3; kx++)
                        xv[ky * 3 + kx] = sX[(ci * 3 + ky) * 114 + w + kx];
#pragma unroll
                for (int k = 0; k < 9; k++) {
                    float xvk = xv[k];
#pragma unroll
                    for (int oc = 0; oc < OFFC; oc++)
                        acc[oc] += xvk * sW[(ci * 9 + k) * OFFC + oc];
                }
            }
        }
        __syncthreads();
    }
    if (w < W) {
#pragma unroll
        for (int oc = 0; oc < OFFC; oc++)
            g_offset[((b * OFFC + oc) * H + h) * W + w] = acc[oc];
    }
}

// ---------------------------------------------------------------------------
// Kernel 2: deformable bilinear sampling, summed over 9 points -> g_sampled
// Block = one (b,h) row, 112 threads (thread = w). Precompute 36 (idx, weight)
// corner pairs in registers, then loop 128 channels with 36 gathers each.
// ---------------------------------------------------------------------------
__device__ __forceinline__ void make_corner(int yi, int xi, float wgt,
                                            int& idx, float& wt) {
    bool valid = (yi >= 0) & (yi < H) & (xi >= 0) & (xi < W);
    int yc = min(max(yi, 0), H - 1);
    int xc = min(max(xi, 0), W - 1);
    idx = yc * W + xc;
    wt = valid ? wgt : 0.f;
}

__global__ void sample_kernel(const float* __restrict__ x) {
    const int h = blockIdx.x;
    const int b = blockIdx.y;
    const int w = threadIdx.x;
    if (w >= W) return;
    const int pix = h * W + w;
    const float* offp = g_offset + (size_t)b * OFFC * H * W + pix;

    int   idx[36];
    float wt[36];
#pragma unroll
    for (int p = 0; p < 9; p++) {
        int ky = p / 3, kx = p % 3;
        float offY = offp[(size_t)p * H * W];
        float offX = offp[(size_t)(9 + p) * H * W];
        float sy = (float)(h + ky - 1) + offY;
        float sx = (float)(w + kx - 1) + offX;
        float fy0 = floorf(sy), fx0 = floorf(sx);
        int y0 = (int)fy0, x0 = (int)fx0;
        float wy = sy - fy0, wx = sx - fx0;
        make_corner(y0,     x0,     (1.f - wy) * (1.f - wx), idx[p*4+0], wt[p*4+0]);
        make_corner(y0,     x0 + 1, (1.f - wy) * wx,         idx[p*4+1], wt[p*4+1]);
        make_corner(y0 + 1, x0,     wy * (1.f - wx),         idx[p*4+2], wt[p*4+2]);
        make_corner(y0 + 1, x0 + 1, wy * wx,                 idx[p*4+3], wt[p*4+3]);
    }

    const float* xb = x + (size_t)b * CIN * H * W;
    float* outb = g_sampled + (size_t)b * CIN * H * W + pix;
#pragma unroll 2
    for (int c = 0; c < CIN; c++) {
        const float* xp = xb + (size_t)c * H * W;
        float acc = 0.f;
#pragma unroll
        for (int q = 0; q < 36; q++) acc += wt[q] * xp[idx[q]];
        outb[(size_t)c * H * W] = acc;
    }
}

// ---------------------------------------------------------------------------
// Kernel 3: main conv  g_sampled(B,128,H,W) * cw(256,128,3,3) -> out
// Block: 64 output channels x full 112-wide row for one (b,h).
// 256 threads: tco in [0,16) -> 4 consecutive co each; tw in [0,16) -> 7 w each.
// Register tile 4co x 7w = 28 accumulators; ~7 FMA per LDS instruction.
// ---------------------------------------------------------------------------
#define CO_TILE 64
#define K3_CK   8
__global__ void __launch_bounds__(256) main_conv_kernel(
        const float* __restrict__ cw, float* __restrict__ out) {
    __shared__ __align__(16) float sIn[K3_CK * 3 * 114];       // [ci][r][j]
    __shared__ __align__(16) float sWt[K3_CK * 9 * CO_TILE];   // [ci][k][co]
    const int cog = blockIdx.x;         // 0..3
    const int h   = blockIdx.y;
    const int b   = blockIdx.z;
    const int tid = threadIdx.x;
    const int tco = tid >> 4;           // 0..15
    const int tw  = tid & 15;           // 0..15
    const int wbase = tw * 7;
    const int co_base = cog * CO_TILE;

    float acc[4][7];
#pragma unroll
    for (int r = 0; r < 4; r++)
#pragma unroll
        for (int i = 0; i < 7; i++) acc[r][i] = 0.f;

    for (int c0 = 0; c0 < CIN; c0 += K3_CK) {
        for (int e = tid; e < K3_CK * 3 * 114; e += 256) {
            int ci  = e / 342;
            int rem = e % 342;
            int r   = rem / 114;
            int j   = rem % 114;
            int row = h - 1 + r;
            int col = j - 1;
            float v = 0.f;
            if (row >= 0 && row < H && col >= 0 && col < W)
                v = g_sampled[((b * CIN + c0 + ci) * H + row) * W + col];
            sIn[e] = v;
        }
        for (int e = tid; e < K3_CK * 9 * CO_TILE; e += 256) {
            int ci  = e / (9 * CO_TILE);
            int rem = e % (9 * CO_TILE);
            int k   = rem / CO_TILE;
            int co  = rem % CO_TILE;
            sWt[e] = cw[((co_base + co) * CIN + c0 + ci) * 9 + k];
        }
        __syncthreads();

#pragma unroll
        for (int ci = 0; ci < K3_CK; ci++) {
#pragma unroll
            for (int ky = 0; ky < 3; ky++) {
                float vals[9];
#pragma unroll
                for (int j = 0; j < 9; j++)
                    vals[j] = sIn[(ci * 3 + ky) * 114 + wbase + j];
#pragma unroll
                for (int kx = 0; kx < 3; kx++) {
                    const float4 wv = *reinterpret_cast<const float4*>(
                        &sWt[(ci * 9 + ky * 3 + kx) * CO_TILE + tco * 4]);
#pragma unroll
                    for (int i = 0; i < 7; i++) {
                        float v = vals[kx + i];
                        acc[0][i] += v * wv.x;
                        acc[1][i] += v * wv.y;
                        acc[2][i] += v * wv.z;
                        acc[3][i] += v * wv.w;
                    }
                }
            }
        }
        __syncthreads();
    }

#pragma unroll
    for (int r = 0; r < 4; r++) {
        int co = co_base + tco * 4 + r;
        float* op = out + (((size_t)b * COUT + co) * H + h) * W + wbase;
#pragma unroll
        for (int i = 0; i < 7; i++) op[i] = acc[r][i];
    }
}

// ---------------------------------------------------------------------------
extern "C" void kernel_launch(void* const* d_in, const int* in_sizes, int n_in,
                              void* d_out, int out_size) {
    const float* x  = (const float*)d_in[0];   // (8,128,112,112)
    const float* ow = (const float*)d_in[1];   // (18,128,3,3)
    const float* ob = (const float*)d_in[2];   // (18)
    const float* cw = (const float*)d_in[3];   // (256,128,3,3)
    float* out = (float*)d_out;                // (8,256,112,112)

    dim3 grid_row(H, BATCH);
    offset_conv_kernel<<<grid_row, 128>>>(x, ow, ob);
    sample_kernel<<<grid_row, 112>>>(x);
    dim3 grid_conv(COUT / CO_TILE, H, BATCH);
    main_conv_kernel<<<grid_conv, 256>>>(cw, out);
}